// round 17
// baseline (speedup 1.0000x reference)
#include <cuda_runtime.h>
#include <cuda_fp16.h>

#define NN 100000
#define MM 32
#define DD 3
#define BB 8

// fs transposed to [n][d][b] fp16: row n = 8 uint2 slots (64 B, aligned).
// slot (2d + half) = 4 batches of fp16; slots 6,7 = explicit zeros.
__device__ __align__(128) uint2 g_fsth[NN * 8];

// 1 if stencil buffer is int64, 0 if int32 (jax x64-disabled downgrade).
__device__ int g_idx_is64;

// ---------------------------------------------------------------------------
// Kernel 1: transpose+compress fs (B,N,D) f32 -> [n][d][b] fp16 rows.
// Thread 0 also detects idx dtype. d==0 thread zeroes pad slots 6,7.
// ---------------------------------------------------------------------------
__global__ void __launch_bounds__(256) transpose_fs_kernel(
    const float* __restrict__ fs, const int* __restrict__ idx32)
{
    int t = blockIdx.x * 256 + threadIdx.x;   // t = n*3 + d
    if (t == 0) {
        int all_zero = 1;
#pragma unroll
        for (int k = 0; k < 64; k++)
            if (idx32[2 * k + 1] != 0) { all_zero = 0; break; }
        g_idx_is64 = all_zero;
    }
    if (t >= NN * DD) return;
    float v[BB];
#pragma unroll
    for (int b = 0; b < BB; b++) v[b] = __ldg(fs + (size_t)b * (NN * DD) + t);
    int n = t / DD;
    int d = t - n * DD;

    __half2 a01 = __floats2half2_rn(v[0], v[1]);
    __half2 a23 = __floats2half2_rn(v[2], v[3]);
    __half2 a45 = __floats2half2_rn(v[4], v[5]);
    __half2 a67 = __floats2half2_rn(v[6], v[7]);
    uint2 u0, u1;
    u0.x = *reinterpret_cast<unsigned int*>(&a01);
    u0.y = *reinterpret_cast<unsigned int*>(&a23);
    u1.x = *reinterpret_cast<unsigned int*>(&a45);
    u1.y = *reinterpret_cast<unsigned int*>(&a67);
    g_fsth[(size_t)n * 8 + d * 2]     = u0;   // d, batches 0-3
    g_fsth[(size_t)n * 8 + d * 2 + 1] = u1;   // d, batches 4-7
    if (d == 0) {
        uint2 z = make_uint2(0u, 0u);
        g_fsth[(size_t)n * 8 + 6] = z;        // zero pads (lanes 6,7 read these)
        g_fsth[(size_t)n * 8 + 7] = z;
    }
}

// ---------------------------------------------------------------------------
// Kernel 2: gather + contraction (R11 core + PDL + software pipelining).
// Block = 256 threads = 32 nodes (8 lanes/node, 4 nodes/warp).
// Gather loop double-buffers groups of 4 LDG.64s: group k+1 issues before
// group k is consumed -> per-thread MLP ~6, hides the ~250cyc L2 latency.
// ---------------------------------------------------------------------------
#define PN 116   // s_w words per node   (116 mod 32 = 20)
#define PD 36    // s_w words per d-row  ( 36 mod 32 =  4)
#define PI 36    // s_idx words per node ( 36 mod 32 =  4)
#define PO 36    // s_out node stride

__global__ void __launch_bounds__(256, 6) rbffd_main_kernel(
    const float* __restrict__ w,        // (N, D, M) f32
    const int* __restrict__ idx32,      // (N, M) int32 or int64 pairs
    float* __restrict__ out)            // (B, N) f32
{
    const unsigned FULL = 0xffffffffu;
    __shared__ __align__(16) float s_w[32 * PN];      // 14848 B
    __shared__ __align__(16) int   s_idx[32 * PI];    //  4608 B
    __shared__ float s_out[BB * PO];                  //  1152 B

    const int node0 = blockIdx.x * 32;
    const int nodeL = threadIdx.x >> 3;               // 0..31 local node
    const int node  = node0 + nodeL;
    const int j     = threadIdx.x & 7;                // lane in node group

    // --- Phase A: stage weights [nl][d][m] (no prepass dependency) ---
    {
        const float4* wsrc = (const float4*)(w + (size_t)node0 * (DD * MM));
#pragma unroll
        for (int p = 0; p < 3; p++) {
            int q = threadIdx.x + p * 256;            // float4 index 0..767
            float4 v = __ldcs(wsrc + q);              // streamed, evict-first
            int nl = q / 24;
            int r  = q % 24;
            int dq = r >> 3;
            int m4 = r & 7;
            *(float4*)(s_w + nl * PN + dq * PD + m4 * 4) = v;
        }
    }

    // --- wait for prepass grid (PDL edge) before touching its outputs ---
    cudaGridDependencySynchronize();

    // --- Phase B: stage this lane's 4 stencil indices (m = 4j..4j+3) ---
    {
        int4 ci;
        if (g_idx_is64) {
            const int* irow = idx32 + (size_t)node * MM * 2;
            ci.x = __ldg(irow + (4 * j + 0) * 2);
            ci.y = __ldg(irow + (4 * j + 1) * 2);
            ci.z = __ldg(irow + (4 * j + 2) * 2);
            ci.w = __ldg(irow + (4 * j + 3) * 2);
        } else {
            ci = __ldg((const int4*)(idx32 + (size_t)node * MM + 4 * j));
        }
        ci.x = ((unsigned)ci.x < (unsigned)NN) ? ci.x : 0;
        ci.y = ((unsigned)ci.y < (unsigned)NN) ? ci.y : 0;
        ci.z = ((unsigned)ci.z < (unsigned)NN) ? ci.z : 0;
        ci.w = ((unsigned)ci.w < (unsigned)NN) ? ci.w : 0;
        *(int4*)(s_idx + nodeL * PI + 4 * j) = ci;
    }

    __syncthreads();

    const int dj = (j < 6) ? (j >> 1) : 2;
    const float* wl = s_w + nodeL * PN + dj * PD;
    const int*   il = s_idx + nodeL * PI;
    const uint2* fb = g_fsth + j;                     // + ridx*8 per gather

    float4 acc = make_float4(0.f, 0.f, 0.f, 0.f);

    // --- software-pipelined gather loop: double-buffered groups of 4 ---
    uint2 pb[4];
    {
        int4 i0 = *(const int4*)(il);
        pb[0] = __ldg(fb + (size_t)i0.x * 8);
        pb[1] = __ldg(fb + (size_t)i0.y * 8);
        pb[2] = __ldg(fb + (size_t)i0.z * 8);
        pb[3] = __ldg(fb + (size_t)i0.w * 8);
    }

#pragma unroll
    for (int mq = 0; mq < 8; mq++) {
        uint2 pn[4];
        if (mq < 7) {
            int4 i4 = *(const int4*)(il + 4 * (mq + 1));
            pn[0] = __ldg(fb + (size_t)i4.x * 8);
            pn[1] = __ldg(fb + (size_t)i4.y * 8);
            pn[2] = __ldg(fb + (size_t)i4.z * 8);
            pn[3] = __ldg(fb + (size_t)i4.w * 8);
        }

        float4 wv = *(const float4*)(wl + 4 * mq);
#pragma unroll
        for (int mi = 0; mi < 4; mi++) {
            float wm = (mi == 0) ? wv.x : (mi == 1) ? wv.y : (mi == 2) ? wv.z : wv.w;
            __half2 h0 = *reinterpret_cast<__half2*>(&pb[mi].x);
            __half2 h1 = *reinterpret_cast<__half2*>(&pb[mi].y);
            float2 f0 = __half22float2(h0);
            float2 f1 = __half22float2(h1);
            acc.x += wm * f0.x;
            acc.y += wm * f0.y;
            acc.z += wm * f1.x;
            acc.w += wm * f1.y;
        }

        if (mq < 7) {
            pb[0] = pn[0]; pb[1] = pn[1]; pb[2] = pn[2]; pb[3] = pn[3];
        }
    }

    // --- reduce over d within the group (lanes 6,7 carry exact zeros) ---
    {
        float a[4] = {acc.x, acc.y, acc.z, acc.w};
#pragma unroll
        for (int c = 0; c < 4; c++) a[c] += __shfl_xor_sync(FULL, a[c], 2, 8);
#pragma unroll
        for (int c = 0; c < 4; c++) a[c] += __shfl_xor_sync(FULL, a[c], 4, 8);
        if (j < 2) {                                  // j=0: b0-3, j=1: b4-7
#pragma unroll
            for (int c = 0; c < 4; c++)
                s_out[(4 * j + c) * PO + nodeL] = a[c];
        }
    }

    __syncthreads();

    // --- coalesced output: warp b writes out[b][node0 .. node0+31] ---
    {
        int b    = threadIdx.x >> 5;                  // 0..7
        int lane = threadIdx.x & 31;
        out[(size_t)b * NN + node0 + lane] = s_out[b * PO + lane];
    }
}

// ---------------------------------------------------------------------------
// Launch. Inputs resolved BY SIZE (element counts distinct):
//   fs = 2,400,000   weights = 9,600,000   idx = 3,200,000
// Main kernel uses PDL so its weight-staging prologue overlaps the prepass.
// ---------------------------------------------------------------------------
extern "C" void kernel_launch(void* const* d_in, const int* in_sizes, int n_in,
                              void* d_out, int out_size) {
    const float* fs  = nullptr;
    const float* w   = nullptr;
    const int*   idx = nullptr;

    for (int i = 0; i < n_in; i++) {
        if (in_sizes[i] == BB * NN * DD)      fs  = (const float*)d_in[i];
        else if (in_sizes[i] == NN * DD * MM) w   = (const float*)d_in[i];
        else if (in_sizes[i] == NN * MM)      idx = (const int*)d_in[i];
    }
    if (!fs)  fs  = (const float*)d_in[0];
    if (!w)   w   = (const float*)d_in[1];
    if (!idx) idx = (const int*)d_in[2];

    float* out = (float*)d_out;

    int t_threads = NN * DD;
    transpose_fs_kernel<<<(t_threads + 255) / 256, 256>>>(fs, idx);

    cudaLaunchConfig_t cfg = {};
    cfg.gridDim  = dim3(NN / 32, 1, 1);               // 3125 blocks
    cfg.blockDim = dim3(256, 1, 1);
    cfg.dynamicSmemBytes = 0;
    cfg.stream = 0;                                   // same (capture) stream
    cudaLaunchAttribute attrs[1];
    attrs[0].id = cudaLaunchAttributeProgrammaticStreamSerialization;
    attrs[0].val.programmaticStreamSerializationAllowed = 1;
    cfg.attrs = attrs;
    cfg.numAttrs = 1;
    cudaLaunchKernelEx(&cfg, rbffd_main_kernel, w, idx, out);
}